// round 13
// baseline (speedup 1.0000x reference)
#include <cuda_runtime.h>
#include <cuda_bf16.h>
#include <math.h>
#include <stdint.h>

#define KP 800               // 784 padded to multiple of 32
#define NB 4096

// zero-initialized device globals: pad region [784,KP) is never written.
__device__ __nv_bfloat16 g_AH[NB * KP];         // feats hi  [B][KP]
__device__ __nv_bfloat16 g_AL[NB * KP];         // feats lo
__device__ __nv_bfloat16 g_WH[256 * KP];        // W1 hi    [256][KP]
__device__ __nv_bfloat16 g_WL[256 * KP];        // W1 lo
__device__ float g_h[NB * 256];                 // hidden   [B][256]

// ---------------------------------------------------------------------------
__device__ __forceinline__ uint32_t pack_bf2(float a, float b) {
    uint32_t lo = (uint32_t)__bfloat16_as_ushort(__float2bfloat16(a));
    uint32_t hi = (uint32_t)__bfloat16_as_ushort(__float2bfloat16(b));
    return lo | (hi << 16);
}

// ---------------------------------------------------------------------------
// Kernel 1: blocks [0,3136): one patch per thread (4096*196/256 = 3136).
//           blocks [3136,3392): W1 -> bf16 hi/lo.
// No shared memory, no block barrier, all 256 threads live.
// ---------------------------------------------------------------------------
#define NPBLK 3136
__global__ __launch_bounds__(256) void prep_kernel(
    const float* __restrict__ x, const float* __restrict__ var_angles,
    const float* __restrict__ W1) {
    uint32_t b = blockIdx.x;
    uint32_t t = threadIdx.x;

    if (b >= NPBLK) {
        int n = b - NPBLK;                   // 0..255
        const float* wrow = W1 + (size_t)n * 784;
        size_t obase = (size_t)n * KP;
        for (int k = t; k < 784; k += 256) {
            float v = wrow[k];
            __nv_bfloat16 h = __float2bfloat16(v);
            g_WH[obase + k] = h;
            g_WL[obase + k] = __float2bfloat16(v - __bfloat162float(h));
        }
        return;
    }

    uint32_t pid = b * 256 + t;              // global patch id
    uint32_t img = pid / 196;
    uint32_t tp  = pid - img * 196;
    uint32_t r = tp / 14, c = tp - r * 14;

    const float* ib = x + (size_t)img * 784;
    float2 top = *(const float2*)(ib + (2 * r) * 28 + 2 * c);
    float2 bot = *(const float2*)(ib + (2 * r + 1) * 28 + 2 * c);

    // uniform angles (broadcast loads)
    float a0 = 0.5f * __ldg(var_angles + 0);
    float a1 = 0.5f * __ldg(var_angles + 1);
    float a2 = 0.5f * __ldg(var_angles + 2);
    float a3 = 0.5f * __ldg(var_angles + 3);
    float cb0, sb0, cb1, sb1, cb2, sb2, cb3, sb3;
    __sincosf(0.5f * __ldg(var_angles + 4), &sb0, &cb0);
    __sincosf(0.5f * __ldg(var_angles + 5), &sb1, &cb1);
    __sincosf(0.5f * __ldg(var_angles + 6), &sb2, &cb2);
    __sincosf(0.5f * __ldg(var_angles + 7), &sb3, &cb3);

    // fused encoder + depth-0 RY: RY(p)RY(a) = RY(p+a)
    float s0, c0, s1, c1, s2, c2, s3, c3;
    __sincosf(0.5f * top.x + a0, &s0, &c0);
    __sincosf(0.5f * top.y + a1, &s1, &c1);
    __sincosf(0.5f * bot.x + a2, &s2, &c2);
    __sincosf(0.5f * bot.y + a3, &s3, &c3);

    // product state sv[i], bit3=wire0 .. bit0=wire3
    float sv[16];
    {
        float ab0 = c0 * c1, ab1 = c0 * s1, ab2 = s0 * c1, ab3 = s0 * s1;
        float cd0 = c2 * c3, cd1 = c2 * s3, cd2 = s2 * c3, cd3 = s2 * s3;
        sv[0] = ab0 * cd0;  sv[1] = ab0 * cd1;  sv[2] = ab0 * cd2;  sv[3] = ab0 * cd3;
        sv[4] = ab1 * cd0;  sv[5] = ab1 * cd1;  sv[6] = ab1 * cd2;  sv[7] = ab1 * cd3;
        sv[8] = ab2 * cd0;  sv[9] = ab2 * cd1;  sv[10] = ab2 * cd2; sv[11] = ab2 * cd3;
        sv[12] = ab3 * cd0; sv[13] = ab3 * cd1; sv[14] = ab3 * cd2; sv[15] = ab3 * cd3;
    }

    // CNOT-ring basis permutation (compile-time relabel)
    const int F[16] = {0, 9, 11, 2, 15, 6, 4, 13, 7, 14, 12, 5, 8, 1, 3, 10};
    float u[16];
    #pragma unroll
    for (int i = 0; i < 16; ++i) u[F[i]] = sv[i];

    // depth-1 RY butterflies (register-resident)
    float CB[4] = {cb0, cb1, cb2, cb3};
    float SB[4] = {sb0, sb1, sb2, sb3};
    #pragma unroll
    for (int w = 0; w < 4; ++w) {
        int m = 8 >> w;
        float cb = CB[w], sb = SB[w];
        #pragma unroll
        for (int i = 0; i < 16; ++i) {
            if (!(i & m)) {
                float t0 = u[i], t1 = u[i | m];
                u[i]     = cb * t0 - sb * t1;
                u[i | m] = sb * t0 + cb * t1;
            }
        }
    }

    // measurement, ring2 permutation folded into signs
    float f0 = 0.f, f1 = 0.f, f2 = 0.f, f3 = 0.f;
    #pragma unroll
    for (int i = 0; i < 16; ++i) {
        float q = u[i] * u[i];
        int fi = F[i];
        f0 += (fi & 8) ? -q : q;
        f1 += (fi & 4) ? -q : q;
        f2 += (fi & 2) ? -q : q;
        f3 += (fi & 1) ? -q : q;
    }

    float h0 = __bfloat162float(__float2bfloat16(f0));
    float h1 = __bfloat162float(__float2bfloat16(f1));
    float h2 = __bfloat162float(__float2bfloat16(f2));
    float h3 = __bfloat162float(__float2bfloat16(f3));
    uint2 H = make_uint2(pack_bf2(f0, f1), pack_bf2(f2, f3));
    uint2 L = make_uint2(pack_bf2(f0 - h0, f1 - h1), pack_bf2(f2 - h2, f3 - h3));
    size_t base = (size_t)img * KP + 4 * tp;
    *(uint2*)&g_AH[base] = H;
    *(uint2*)&g_AL[base] = L;
}

// ---------------------------------------------------------------------------
// Kernel 2: H = relu(A @ W1^T + b1), bf16x3 HMMA GEMM.
// BM=64, BN=64, BK=32, 256 threads (8 warps, 4x2), warp tile 16x32,
// 3-stage cp.async pipeline. grid = (4, 64) = 256 CTAs.
// ---------------------------------------------------------------------------
#define STG 16384
#define OFF_AH 0
#define OFF_AL 4096
#define OFF_WH 8192
#define OFF_WL 12288
#define NKT 25               // KP / 32

__device__ __forceinline__ void ldsm4(uint32_t* r, uint32_t a) {
    asm volatile("ldmatrix.sync.aligned.m8n8.x4.shared.b16 {%0,%1,%2,%3}, [%4];\n"
                 : "=r"(r[0]), "=r"(r[1]), "=r"(r[2]), "=r"(r[3]) : "r"(a));
}
__device__ __forceinline__ void mma16816(float* d, const uint32_t* a, uint32_t b0, uint32_t b1) {
    asm volatile(
        "mma.sync.aligned.m16n8k16.row.col.f32.bf16.bf16.f32 "
        "{%0,%1,%2,%3}, {%4,%5,%6,%7}, {%8,%9}, {%0,%1,%2,%3};\n"
        : "+f"(d[0]), "+f"(d[1]), "+f"(d[2]), "+f"(d[3])
        : "r"(a[0]), "r"(a[1]), "r"(a[2]), "r"(a[3]), "r"(b0), "r"(b1));
}
__device__ __forceinline__ void cp16(uint32_t dst, const void* src) {
    asm volatile("cp.async.cg.shared.global [%0], [%1], 16;\n" :: "r"(dst), "l"(src));
}

__global__ __launch_bounds__(256) void gemm1_kernel(const float* __restrict__ b1) {
    __shared__ __align__(16) unsigned char smem[3 * STG];
    uint32_t sbase = (uint32_t)__cvta_generic_to_shared(smem);
    int t = threadIdx.x;
    int bm = blockIdx.y, bn = blockIdx.x;
    int warp = t >> 5, lane = t & 31;
    int wm = warp >> 1, wn = warp & 1;

    int row = t >> 2, ch = t & 3;
    uint32_t sw = (uint32_t)(row * 64 + ((ch ^ ((row >> 1) & 3)) << 4));
    const size_t a_goff = (size_t)(bm * 64 + row) * KP + ch * 8;
    const size_t w_goff = (size_t)(bn * 64 + row) * KP + ch * 8;

    float acc[4][4];
    #pragma unroll
    for (int nj = 0; nj < 4; ++nj)
        #pragma unroll
        for (int e = 0; e < 4; ++e) acc[nj][e] = 0.f;

    #pragma unroll
    for (int s = 0; s < 2; ++s) {
        uint32_t B = sbase + s * STG;
        int k0 = s * 32;
        cp16(B + OFF_AH + sw, g_AH + a_goff + k0);
        cp16(B + OFF_AL + sw, g_AL + a_goff + k0);
        cp16(B + OFF_WH + sw, g_WH + w_goff + k0);
        cp16(B + OFF_WL + sw, g_WL + w_goff + k0);
        asm volatile("cp.async.commit_group;\n");
    }

    int grp = lane >> 3, li = lane & 7;
    for (int kt = 0; kt < NKT; ++kt) {
        if (kt < NKT - 1) asm volatile("cp.async.wait_group 1;\n");
        else              asm volatile("cp.async.wait_group 0;\n");
        __syncthreads();

        if (kt + 2 < NKT) {
            uint32_t B = sbase + ((kt + 2) % 3) * STG;
            int k0 = (kt + 2) * 32;
            cp16(B + OFF_AH + sw, g_AH + a_goff + k0);
            cp16(B + OFF_AL + sw, g_AL + a_goff + k0);
            cp16(B + OFF_WH + sw, g_WH + w_goff + k0);
            cp16(B + OFF_WL + sw, g_WL + w_goff + k0);
            asm volatile("cp.async.commit_group;\n");
        }

        uint32_t B = sbase + (kt % 3) * STG;
        #pragma unroll
        for (int ks = 0; ks < 2; ++ks) {
            int ko = ks * 16;
            uint32_t ah[4], al[4], bh[2][4], bl[2][4];
            {
                int r = wm * 16 + li + ((grp & 1) << 3);
                int ke = ko + ((grp >> 1) << 3);
                uint32_t off = (uint32_t)(r * 64 + (((ke >> 3) ^ ((r >> 1) & 3)) << 4));
                ldsm4(ah, B + OFF_AH + off);
                ldsm4(al, B + OFF_AL + off);
            }
            int rb_l = li + ((grp >> 1) << 3);
            int keb = ko + ((grp & 1) << 3);
            #pragma unroll
            for (int nt = 0; nt < 2; ++nt) {
                int r = wn * 32 + nt * 16 + rb_l;
                uint32_t off = (uint32_t)(r * 64 + (((keb >> 3) ^ ((r >> 1) & 3)) << 4));
                ldsm4(bh[nt], B + OFF_WH + off);
                ldsm4(bl[nt], B + OFF_WL + off);
            }
            #pragma unroll
            for (int nj = 0; nj < 4; ++nj) {
                int nt = nj >> 1, hf = nj & 1;
                mma16816(acc[nj], ah, bh[nt][hf * 2], bh[nt][hf * 2 + 1]);
                mma16816(acc[nj], ah, bl[nt][hf * 2], bl[nt][hf * 2 + 1]);
                mma16816(acc[nj], al, bh[nt][hf * 2], bh[nt][hf * 2 + 1]);
            }
        }
        __syncthreads();
    }

    int mrow = bm * 64 + wm * 16 + (lane >> 2);
    int ncol0 = bn * 64 + wn * 32 + (lane & 3) * 2;
    #pragma unroll
    for (int nj = 0; nj < 4; ++nj) {
        int col = ncol0 + nj * 8;
        float bb0 = __ldg(b1 + col), bb1 = __ldg(b1 + col + 1);
        float2 v0 = make_float2(fmaxf(acc[nj][0] + bb0, 0.f),
                                fmaxf(acc[nj][1] + bb1, 0.f));
        float2 v1 = make_float2(fmaxf(acc[nj][2] + bb0, 0.f),
                                fmaxf(acc[nj][3] + bb1, 0.f));
        *(float2*)&g_h[(size_t)mrow * 256 + col] = v0;
        *(float2*)&g_h[(size_t)(mrow + 8) * 256 + col] = v1;
    }
}

// ---------------------------------------------------------------------------
// Kernel 3: logits + log_softmax. 32 rows/block, one warp per row.
// ---------------------------------------------------------------------------
__global__ __launch_bounds__(1024) void head_kernel(
    const float* __restrict__ W2, const float* __restrict__ b2,
    float* __restrict__ out) {
    __shared__ float sW[2560];
    __shared__ float sb[10];
    int t = threadIdx.x;
    for (int i = t; i < 2560; i += 1024) sW[i] = W2[i];
    if (t < 10) sb[t] = b2[t];
    __syncthreads();

    int warp = t >> 5, lane = t & 31;
    int m = blockIdx.x * 32 + warp;
    const float* hr = g_h + (size_t)m * 256;

    float h8[8];
    #pragma unroll
    for (int i = 0; i < 8; ++i) h8[i] = hr[lane + 32 * i];

    float p[10];
    #pragma unroll
    for (int j = 0; j < 10; ++j) {
        float s = 0.f;
        #pragma unroll
        for (int i = 0; i < 8; ++i) s += h8[i] * sW[j * 256 + lane + 32 * i];
        p[j] = s;
    }
    #pragma unroll
    for (int o = 16; o > 0; o >>= 1)
        #pragma unroll
        for (int j = 0; j < 10; ++j) p[j] += __shfl_xor_sync(0xffffffffu, p[j], o);
    #pragma unroll
    for (int j = 0; j < 10; ++j) p[j] += sb[j];

    float mx = p[0];
    #pragma unroll
    for (int j = 1; j < 10; ++j) mx = fmaxf(mx, p[j]);
    float sum = 0.f;
    #pragma unroll
    for (int j = 0; j < 10; ++j) sum += expf(p[j] - mx);
    float lse = mx + logf(sum);

    if (lane < 10) {
        float v;
        switch (lane) {
            case 0: v = p[0]; break; case 1: v = p[1]; break;
            case 2: v = p[2]; break; case 3: v = p[3]; break;
            case 4: v = p[4]; break; case 5: v = p[5]; break;
            case 6: v = p[6]; break; case 7: v = p[7]; break;
            case 8: v = p[8]; break; default: v = p[9]; break;
        }
        out[m * 10 + lane] = v - lse;
    }
}

// ---------------------------------------------------------------------------
extern "C" void kernel_launch(void* const* d_in, const int* in_sizes, int n_in,
                              void* d_out, int out_size) {
    const float* x   = (const float*)d_in[0];
    const float* var = (const float*)d_in[1];
    const float* W1  = (const float*)d_in[2];
    const float* b1  = (const float*)d_in[3];
    const float* W2  = (const float*)d_in[4];
    const float* b2  = (const float*)d_in[5];
    float* out = (float*)d_out;

    int B = in_sizes[0] / 784;                  // 4096

    prep_kernel<<<NPBLK + 256, 256>>>(x, var, W1);
    dim3 grid1(4, B / 64);
    gemm1_kernel<<<grid1, 256>>>(b1);
    head_kernel<<<B / 32, 1024>>>(W2, b2, out);
}

// round 16
// speedup vs baseline: 1.1106x; 1.1106x over previous
#include <cuda_runtime.h>
#include <cuda_bf16.h>
#include <math.h>
#include <stdint.h>

#define KP 800               // 784 padded to multiple of 32
#define NB 4096

// zero-initialized device globals: pad region [784,KP) is never written.
__device__ __nv_bfloat16 g_AH[NB * KP];
__device__ __nv_bfloat16 g_AL[NB * KP];
__device__ __nv_bfloat16 g_WH[256 * KP];
__device__ __nv_bfloat16 g_WL[256 * KP];
__device__ float g_h[NB * 256];

// ---------------------------------------------------------------------------
__device__ __forceinline__ uint32_t pack_bf2(float a, float b) {
    uint32_t lo = (uint32_t)__bfloat16_as_ushort(__float2bfloat16(a));
    uint32_t hi = (uint32_t)__bfloat16_as_ushort(__float2bfloat16(b));
    return lo | (hi << 16);
}
__device__ __forceinline__ unsigned long long pk64(float lo, float hi) {
    unsigned long long r;
    asm("mov.b64 %0, {%1, %2};" : "=l"(r) : "f"(lo), "f"(hi));
    return r;
}
__device__ __forceinline__ void upk64(float& lo, float& hi, unsigned long long v) {
    asm("mov.b64 {%0, %1}, %2;" : "=f"(lo), "=f"(hi) : "l"(v));
}
__device__ __forceinline__ unsigned long long fma2(unsigned long long a,
                                                   unsigned long long b,
                                                   unsigned long long c) {
    unsigned long long d;
    asm("fma.rn.f32x2 %0, %1, %2, %3;" : "=l"(d) : "l"(a), "l"(b), "l"(c));
    return d;
}

// ---------------------------------------------------------------------------
// Kernel 1: blocks [0,1568): TWO consecutive patches per thread.
//           blocks [1568,1824): W1 -> bf16 hi/lo.
// Circuit: RY(p)RY(a0)=RY(p+a0); ring1 = compile-time permutation F; depth-1
// RY = butterflies (3 packed f32x2 levels + in-pair level fused w/ squares);
// ring2 folded into measurement signs (qs/qd pair reductions).
// ---------------------------------------------------------------------------
#define NPBLK 1568
struct Ctx {
    float a0, a1, a2, a3;                 // 0.5 * var_angles[0][w]
    unsigned long long CP[3], SP[3], NP[3], Z0;
    float cb3, sb3;
};

__device__ __forceinline__ void quanv_patch(const Ctx& cx,
                                            float p0, float p1, float p2, float p3,
                                            uint2& H, uint2& L) {
    float s0, c0, s1, c1, s2, c2, s3, c3;
    __sincosf(0.5f * p0 + cx.a0, &s0, &c0);
    __sincosf(0.5f * p1 + cx.a1, &s1, &c1);
    __sincosf(0.5f * p2 + cx.a2, &s2, &c2);
    __sincosf(0.5f * p3 + cx.a3, &s3, &c3);

    float sv[16];
    {
        float ab0 = c0 * c1, ab1 = c0 * s1, ab2 = s0 * c1, ab3 = s0 * s1;
        float cd0 = c2 * c3, cd1 = c2 * s3, cd2 = s2 * c3, cd3 = s2 * s3;
        sv[0] = ab0 * cd0;  sv[1] = ab0 * cd1;  sv[2] = ab0 * cd2;  sv[3] = ab0 * cd3;
        sv[4] = ab1 * cd0;  sv[5] = ab1 * cd1;  sv[6] = ab1 * cd2;  sv[7] = ab1 * cd3;
        sv[8] = ab2 * cd0;  sv[9] = ab2 * cd1;  sv[10] = ab2 * cd2; sv[11] = ab2 * cd3;
        sv[12] = ab3 * cd0; sv[13] = ab3 * cd1; sv[14] = ab3 * cd2; sv[15] = ab3 * cd3;
    }

    // ring1 permutation (register relabel)
    const int F[16] = {0, 9, 11, 2, 15, 6, 4, 13, 7, 14, 12, 5, 8, 1, 3, 10};
    float u[16];
    #pragma unroll
    for (int i = 0; i < 16; ++i) u[F[i]] = sv[i];

    // pack pairs: P[p] = (u[2p], u[2p+1])
    unsigned long long P[8];
    #pragma unroll
    for (int p = 0; p < 8; ++p) P[p] = pk64(u[2 * p], u[2 * p + 1]);

    // packed butterflies for wires 0..2 (pair-space masks 4,2,1)
    #pragma unroll
    for (int lvl = 0; lvl < 3; ++lvl) {
        int mp = 4 >> lvl;
        unsigned long long cb = cx.CP[lvl], sb = cx.SP[lvl], nb = cx.NP[lvl];
        #pragma unroll
        for (int p = 0; p < 8; ++p) {
            if (!(p & mp)) {
                int q = p | mp;
                unsigned long long t = fma2(cb, P[p], cx.Z0);
                t = fma2(nb, P[q], t);
                unsigned long long r2 = fma2(sb, P[p], cx.Z0);
                r2 = fma2(cb, P[q], r2);
                P[p] = t; P[q] = r2;
            }
        }
    }

    // wire 3 (in-pair rotation) fused with squares -> qs/qd per pair
    float qs[8], qd[8];
    #pragma unroll
    for (int p = 0; p < 8; ++p) {
        float xx, yy; upk64(xx, yy, P[p]);
        float u0 = cx.cb3 * xx - cx.sb3 * yy;
        float u1 = cx.sb3 * xx + cx.cb3 * yy;
        float q0 = u0 * u0, q1 = u1 * u1;
        qs[p] = q0 + q1;
        qd[p] = q0 - q1;
    }

    // ring2-folded signs (derived from bits of F, re-verified by enumeration)
    float A = qd[0] - qd[1] - qd[2] + qd[3];
    float Bd = qd[4] - qd[5] - qd[6] + qd[7];
    float f0 = A + Bd;
    float f3 = A - Bd;
    float f1 = (qs[0] + qs[1]) - (qs[2] + qs[3]) - (qs[4] + qs[5]) + (qs[6] + qs[7]);
    float f2 = (qs[0] - qs[1]) + (qs[3] - qs[2]) + (qs[5] - qs[4]) + (qs[6] - qs[7]);

    float h0 = __bfloat162float(__float2bfloat16(f0));
    float h1 = __bfloat162float(__float2bfloat16(f1));
    float h2 = __bfloat162float(__float2bfloat16(f2));
    float h3 = __bfloat162float(__float2bfloat16(f3));
    H = make_uint2(pack_bf2(f0, f1), pack_bf2(f2, f3));
    L = make_uint2(pack_bf2(f0 - h0, f1 - h1), pack_bf2(f2 - h2, f3 - h3));
}

__global__ __launch_bounds__(256) void prep_kernel(
    const float* __restrict__ x, const float* __restrict__ var_angles,
    const float* __restrict__ W1) {
    uint32_t b = blockIdx.x;
    uint32_t t = threadIdx.x;

    if (b >= NPBLK) {
        int n = b - NPBLK;                   // 0..255
        const float* wrow = W1 + (size_t)n * 784;
        size_t obase = (size_t)n * KP;
        for (int k = t; k < 784; k += 256) {
            float v = wrow[k];
            __nv_bfloat16 h = __float2bfloat16(v);
            g_WH[obase + k] = h;
            g_WL[obase + k] = __float2bfloat16(v - __bfloat162float(h));
        }
        return;
    }

    // uniform circuit context (broadcast loads, warp-uniform)
    Ctx cx;
    cx.a0 = 0.5f * __ldg(var_angles + 0);
    cx.a1 = 0.5f * __ldg(var_angles + 1);
    cx.a2 = 0.5f * __ldg(var_angles + 2);
    cx.a3 = 0.5f * __ldg(var_angles + 3);
    #pragma unroll
    for (int w = 0; w < 3; ++w) {
        float cb, sb;
        __sincosf(0.5f * __ldg(var_angles + 4 + w), &sb, &cb);
        cx.CP[w] = pk64(cb, cb);
        cx.SP[w] = pk64(sb, sb);
        cx.NP[w] = pk64(-sb, -sb);
    }
    __sincosf(0.5f * __ldg(var_angles + 7), &cx.sb3, &cx.cb3);
    cx.Z0 = 0ull;

    uint32_t pp = b * 256 + t;               // patch-pair id (0..401407)
    uint32_t img = pp / 98;
    uint32_t pr  = pp - img * 98;            // pair within image
    uint32_t tp0 = 2 * pr;                   // first patch id (even)
    uint32_t r = tp0 / 14, c0 = tp0 - r * 14;

    const float* ib = x + (size_t)img * 784;
    float4 top = *(const float4*)(ib + (2 * r) * 28 + 2 * c0);
    float4 bot = *(const float4*)(ib + (2 * r + 1) * 28 + 2 * c0);

    uint2 H0, L0, H1, L1;
    quanv_patch(cx, top.x, top.y, bot.x, bot.y, H0, L0);
    quanv_patch(cx, top.z, top.w, bot.z, bot.w, H1, L1);

    size_t base = (size_t)img * KP + 4 * tp0;   // 16B aligned (tp0 even, KP%8==0)
    *(uint4*)&g_AH[base] = make_uint4(H0.x, H0.y, H1.x, H1.y);
    *(uint4*)&g_AL[base] = make_uint4(L0.x, L0.y, L1.x, L1.y);
}

// ---------------------------------------------------------------------------
// Kernel 2: H = relu(A @ W1^T + b1), bf16x3 HMMA GEMM.  (proven round-13 ver.)
// BM=64, BN=64, BK=32, 256 threads (8 warps, 4x2), warp tile 16x32,
// 3-stage cp.async pipeline, static 48KB smem. grid = (4, 64) = 256 CTAs.
// ---------------------------------------------------------------------------
#define STG 16384
#define OFF_AH 0
#define OFF_AL 4096
#define OFF_WH 8192
#define OFF_WL 12288
#define NKT 25               // KP / 32

__device__ __forceinline__ void ldsm4(uint32_t* r, uint32_t a) {
    asm volatile("ldmatrix.sync.aligned.m8n8.x4.shared.b16 {%0,%1,%2,%3}, [%4];\n"
                 : "=r"(r[0]), "=r"(r[1]), "=r"(r[2]), "=r"(r[3]) : "r"(a));
}
__device__ __forceinline__ void mma16816(float* d, const uint32_t* a, uint32_t b0, uint32_t b1) {
    asm volatile(
        "mma.sync.aligned.m16n8k16.row.col.f32.bf16.bf16.f32 "
        "{%0,%1,%2,%3}, {%4,%5,%6,%7}, {%8,%9}, {%0,%1,%2,%3};\n"
        : "+f"(d[0]), "+f"(d[1]), "+f"(d[2]), "+f"(d[3])
        : "r"(a[0]), "r"(a[1]), "r"(a[2]), "r"(a[3]), "r"(b0), "r"(b1));
}
__device__ __forceinline__ void cp16(uint32_t dst, const void* src) {
    asm volatile("cp.async.cg.shared.global [%0], [%1], 16;\n" :: "r"(dst), "l"(src));
}

__global__ __launch_bounds__(256) void gemm1_kernel(const float* __restrict__ b1) {
    __shared__ __align__(16) unsigned char smem[3 * STG];
    uint32_t sbase = (uint32_t)__cvta_generic_to_shared(smem);
    int t = threadIdx.x;
    int bm = blockIdx.y, bn = blockIdx.x;
    int warp = t >> 5, lane = t & 31;
    int wm = warp >> 1, wn = warp & 1;

    int row = t >> 2, ch = t & 3;
    uint32_t sw = (uint32_t)(row * 64 + ((ch ^ ((row >> 1) & 3)) << 4));
    const size_t a_goff = (size_t)(bm * 64 + row) * KP + ch * 8;
    const size_t w_goff = (size_t)(bn * 64 + row) * KP + ch * 8;

    float acc[4][4];
    #pragma unroll
    for (int nj = 0; nj < 4; ++nj)
        #pragma unroll
        for (int e = 0; e < 4; ++e) acc[nj][e] = 0.f;

    #pragma unroll
    for (int s = 0; s < 2; ++s) {
        uint32_t B = sbase + s * STG;
        int k0 = s * 32;
        cp16(B + OFF_AH + sw, g_AH + a_goff + k0);
        cp16(B + OFF_AL + sw, g_AL + a_goff + k0);
        cp16(B + OFF_WH + sw, g_WH + w_goff + k0);
        cp16(B + OFF_WL + sw, g_WL + w_goff + k0);
        asm volatile("cp.async.commit_group;\n");
    }

    int grp = lane >> 3, li = lane & 7;
    for (int kt = 0; kt < NKT; ++kt) {
        if (kt < NKT - 1) asm volatile("cp.async.wait_group 1;\n");
        else              asm volatile("cp.async.wait_group 0;\n");
        __syncthreads();

        if (kt + 2 < NKT) {
            uint32_t B = sbase + ((kt + 2) % 3) * STG;
            int k0 = (kt + 2) * 32;
            cp16(B + OFF_AH + sw, g_AH + a_goff + k0);
            cp16(B + OFF_AL + sw, g_AL + a_goff + k0);
            cp16(B + OFF_WH + sw, g_WH + w_goff + k0);
            cp16(B + OFF_WL + sw, g_WL + w_goff + k0);
            asm volatile("cp.async.commit_group;\n");
        }

        uint32_t B = sbase + (kt % 3) * STG;
        #pragma unroll
        for (int ks = 0; ks < 2; ++ks) {
            int ko = ks * 16;
            uint32_t ah[4], al[4], bh[2][4], bl[2][4];
            {
                int r = wm * 16 + li + ((grp & 1) << 3);
                int ke = ko + ((grp >> 1) << 3);
                uint32_t off = (uint32_t)(r * 64 + (((ke >> 3) ^ ((r >> 1) & 3)) << 4));
                ldsm4(ah, B + OFF_AH + off);
                ldsm4(al, B + OFF_AL + off);
            }
            int rb_l = li + ((grp >> 1) << 3);
            int keb = ko + ((grp & 1) << 3);
            #pragma unroll
            for (int nt = 0; nt < 2; ++nt) {
                int r = wn * 32 + nt * 16 + rb_l;
                uint32_t off = (uint32_t)(r * 64 + (((keb >> 3) ^ ((r >> 1) & 3)) << 4));
                ldsm4(bh[nt], B + OFF_WH + off);
                ldsm4(bl[nt], B + OFF_WL + off);
            }
            #pragma unroll
            for (int nj = 0; nj < 4; ++nj) {
                int nt = nj >> 1, hf = nj & 1;
                mma16816(acc[nj], ah, bh[nt][hf * 2], bh[nt][hf * 2 + 1]);
                mma16816(acc[nj], ah, bl[nt][hf * 2], bl[nt][hf * 2 + 1]);
                mma16816(acc[nj], al, bh[nt][hf * 2], bh[nt][hf * 2 + 1]);
            }
        }
        __syncthreads();
    }

    int mrow = bm * 64 + wm * 16 + (lane >> 2);
    int ncol0 = bn * 64 + wn * 32 + (lane & 3) * 2;
    #pragma unroll
    for (int nj = 0; nj < 4; ++nj) {
        int col = ncol0 + nj * 8;
        float bb0 = __ldg(b1 + col), bb1 = __ldg(b1 + col + 1);
        float2 v0 = make_float2(fmaxf(acc[nj][0] + bb0, 0.f),
                                fmaxf(acc[nj][1] + bb1, 0.f));
        float2 v1 = make_float2(fmaxf(acc[nj][2] + bb0, 0.f),
                                fmaxf(acc[nj][3] + bb1, 0.f));
        *(float2*)&g_h[(size_t)mrow * 256 + col] = v0;
        *(float2*)&g_h[(size_t)(mrow + 8) * 256 + col] = v1;
    }
}

// ---------------------------------------------------------------------------
// Kernel 3: logits + log_softmax. 32 rows/block, one warp per row.
// ---------------------------------------------------------------------------
__global__ __launch_bounds__(1024) void head_kernel(
    const float* __restrict__ W2, const float* __restrict__ b2,
    float* __restrict__ out) {
    __shared__ float sW[2560];
    __shared__ float sb[10];
    int t = threadIdx.x;
    for (int i = t; i < 2560; i += 1024) sW[i] = W2[i];
    if (t < 10) sb[t] = b2[t];
    __syncthreads();

    int warp = t >> 5, lane = t & 31;
    int m = blockIdx.x * 32 + warp;
    const float* hr = g_h + (size_t)m * 256;

    float h8[8];
    #pragma unroll
    for (int i = 0; i < 8; ++i) h8[i] = hr[lane + 32 * i];

    float p[10];
    #pragma unroll
    for (int j = 0; j < 10; ++j) {
        float s = 0.f;
        #pragma unroll
        for (int i = 0; i < 8; ++i) s += h8[i] * sW[j * 256 + lane + 32 * i];
        p[j] = s;
    }
    #pragma unroll
    for (int o = 16; o > 0; o >>= 1)
        #pragma unroll
        for (int j = 0; j < 10; ++j) p[j] += __shfl_xor_sync(0xffffffffu, p[j], o);
    #pragma unroll
    for (int j = 0; j < 10; ++j) p[j] += sb[j];

    float mx = p[0];
    #pragma unroll
    for (int j = 1; j < 10; ++j) mx = fmaxf(mx, p[j]);
    float sum = 0.f;
    #pragma unroll
    for (int j = 0; j < 10; ++j) sum += expf(p[j] - mx);
    float lse = mx + logf(sum);

    if (lane < 10) {
        float v;
        switch (lane) {
            case 0: v = p[0]; break; case 1: v = p[1]; break;
            case 2: v = p[2]; break; case 3: v = p[3]; break;
            case 4: v = p[4]; break; case 5: v = p[5]; break;
            case 6: v = p[6]; break; case 7: v = p[7]; break;
            case 8: v = p[8]; break; default: v = p[9]; break;
        }
        out[m * 10 + lane] = v - lse;
    }
}

// ---------------------------------------------------------------------------
extern "C" void kernel_launch(void* const* d_in, const int* in_sizes, int n_in,
                              void* d_out, int out_size) {
    const float* x   = (const float*)d_in[0];
    const float* var = (const float*)d_in[1];
    const float* W1  = (const float*)d_in[2];
    const float* b1  = (const float*)d_in[3];
    const float* W2  = (const float*)d_in[4];
    const float* b2  = (const float*)d_in[5];
    float* out = (float*)d_out;

    int B = in_sizes[0] / 784;                  // 4096

    prep_kernel<<<NPBLK + 256, 256>>>(x, var, W1);
    dim3 grid1(4, B / 64);
    gemm1_kernel<<<grid1, 256>>>(b1);
    head_kernel<<<B / 32, 1024>>>(W2, b2, out);
}